// round 9
// baseline (speedup 1.0000x reference)
#include <cuda_runtime.h>

// E[b] = sum_p decompFE_flat[b,p] * rsqrt(|coords[b,i(p)]-coords[b,j(p)]|^2)
//
// Two-phase per block (one batch per block):
//  Phase 1: compute recip_r for all 4950 pairs into smem (jblk-major,
//           lane-resident j coords, no gmem in the loop).
//  Phase 2: dot(flat_row, recip) with independent float2 LDGs -> high MLP.

#define BATCH   2048
#define NATOMS  100
#define NC2     4950
#define TPB     256
#define NWARPS  (TPB / 32)

__global__ __launch_bounds__(TPB, 8)
void eij_kernel(const float* __restrict__ coords,
                const float* __restrict__ flat,
                float* __restrict__ out)
{
    __shared__ float4 sc4[NATOMS];        // coords, padded float4
    __shared__ float  recip[NC2];         // 19.8 KB
    __shared__ float  wred[NWARPS];

    const int b    = blockIdx.x;
    const int t    = threadIdx.x;
    const int lane = t & 31;
    const int wid  = t >> 5;

    // stage coords
    {
        float* scf = (float*)sc4;
        const float* cb = coords + (size_t)b * (NATOMS * 3);
        for (int k = t; k < NATOMS * 3; k += TPB) {
            const int a = k / 3, c = k - a * 3;
            scf[a * 4 + c] = cb[k];
        }
    }
    __syncthreads();

    // ---- Phase 1: fill recip[] ----
    #pragma unroll
    for (int jb = 0; jb < 4; ++jb) {
        const int jbase = jb * 32;
        const int j = jbase + lane;

        float xj = 0.f, yj = 0.f, zj = 0.f;
        if (j < NATOMS) {
            const float4 cj = sc4[j];
            xj = cj.x; yj = cj.y; zj = cj.z;
        }

        int i   = jbase + 1 + wid;
        int off = i * (i - 1) / 2 + jbase + lane;

        #pragma unroll 4
        for (; i < NATOMS; i += NWARPS, off += 8 * i - 36) {
            const float4 ci = sc4[i];           // warp-uniform LDS.128
            float dx = ci.x - xj, dy = ci.y - yj, dz = ci.z - zj;
            float r2 = fmaf(dx, dx, fmaf(dy, dy, dz * dz));
            float rr = rsqrtf(r2);
            if (lane < (i - jbase)) recip[off] = rr;
        }
    }
    __syncthreads();

    // ---- Phase 2: dot product, float2 streams (row stride 19800 B, 8B-aligned) ----
    const float2* fb2 = (const float2*)(flat + (size_t)b * NC2);
    const float2* rp2 = (const float2*)recip;

    float a = 0.0f;
    for (int p = t; p < NC2 / 2; p += TPB) {
        const float2 v = __ldcs(fb2 + p);
        const float2 r = rp2[p];
        a = fmaf(v.x, r.x, a);
        a = fmaf(v.y, r.y, a);
    }

    // reduction
    #pragma unroll
    for (int off = 16; off > 0; off >>= 1)
        a += __shfl_down_sync(0xFFFFFFFFu, a, off);
    if (lane == 0) wred[wid] = a;
    __syncthreads();

    if (wid == 0) {
        float s = (lane < NWARPS) ? wred[lane] : 0.0f;
        #pragma unroll
        for (int off = NWARPS / 2; off > 0; off >>= 1)
            s += __shfl_down_sync(0xFFu, s, off);
        if (lane == 0) out[b] = s;
    }
}

extern "C" void kernel_launch(void* const* d_in, const int* in_sizes, int n_in,
                              void* d_out, int out_size)
{
    const float* coords = (const float*)d_in[0];   // [2048, 100, 3]
    const float* flat   = (const float*)d_in[1];   // [2048, 4950]
    float* out          = (float*)d_out;           // [2048, 1]

    eij_kernel<<<BATCH, TPB>>>(coords, flat, out);
}

// round 10
// speedup vs baseline: 1.2429x; 1.2429x over previous
#include <cuda_runtime.h>
#include <cstdint>

// E[b] = sum over strict-lower-tri pairs (i,j) (row-major flat order):
//          decompFE_flat[b,p] * rsqrt(|coords[b,i]-coords[b,j]|^2)
//
// Latency fix: each block bulk-copies its 2 flat rows (39600 B, 16B-aligned)
// into smem via cp.async.bulk + mbarrier (copy-engine MLP, no register cost),
// then runs the fused pair loop reading v from SMEM (29-cyc LDS, no DRAM
// stalls in the loop). BPB=2, lane-resident j coords, LDS.128 i coords.

#define BATCH   2048
#define NATOMS  100
#define NC2     4950
#define TPB     256
#define NWARPS  (TPB / 32)
#define BPB     2
#define COPY_BYTES (BPB * NC2 * 4)      // 39600, multiple of 16

__device__ __forceinline__ uint32_t smem_u32(const void* p) {
    uint32_t a;
    asm("{ .reg .u64 t; cvta.to.shared.u64 t, %1; cvt.u32.u64 %0, t; }"
        : "=r"(a) : "l"(p));
    return a;
}

__global__ __launch_bounds__(TPB)
void eij_kernel(const float* __restrict__ coords,
                const float* __restrict__ flat,
                float* __restrict__ out)
{
    __shared__ float sflat[BPB * NC2];            // 39600 B
    __shared__ float sc[NATOMS * 8];              // [atom*8 + q*4 + c]
    __shared__ float wred[BPB][NWARPS];
    __shared__ __align__(8) unsigned long long mbar;

    const int b0   = blockIdx.x * BPB;
    const int t    = threadIdx.x;
    const int lane = t & 31;
    const int wid  = t >> 5;

    const uint32_t mb = smem_u32(&mbar);

    if (t == 0) {
        asm volatile("mbarrier.init.shared.b64 [%0], 1;" :: "r"(mb) : "memory");
    }
    __syncthreads();

    if (t == 0) {
        const uint32_t dst = smem_u32(sflat);
        const float* src = flat + (size_t)b0 * NC2;   // b0 even -> 16B aligned
        asm volatile("mbarrier.arrive.expect_tx.shared.b64 _, [%0], %1;"
                     :: "r"(mb), "r"((unsigned)COPY_BYTES) : "memory");
        asm volatile("cp.async.bulk.shared::cta.global.mbarrier::complete_tx::bytes"
                     " [%0], [%1], %2, [%3];"
                     :: "r"(dst), "l"(src), "r"((unsigned)COPY_BYTES), "r"(mb)
                     : "memory");
    }

    // stage coords while the bulk copy flies (interleaved [atom][q][4])
    for (int k = t; k < NATOMS * 3 * BPB; k += TPB) {
        const int q    = k / (NATOMS * 3);
        const int r    = k - q * (NATOMS * 3);
        const int atom = r / 3;
        const int c    = r - atom * 3;
        sc[atom * 8 + q * 4 + c] = coords[(size_t)(b0 + q) * (NATOMS * 3) + r];
    }
    __syncthreads();

    // wait for the flat tile
    {
        uint32_t done;
        do {
            asm volatile("{ .reg .pred p;"
                         "  mbarrier.try_wait.parity.shared.b64 p, [%1], 0, 0x989680;"
                         "  selp.b32 %0, 1, 0, p; }"
                         : "=r"(done) : "r"(mb) : "memory");
        } while (!done);
    }

    float acc0 = 0.0f, acc1 = 0.0f;

    #pragma unroll
    for (int jb = 0; jb < 4; ++jb) {
        const int jbase = jb * 32;
        const int j = jbase + lane;

        float xj0 = 0.f, yj0 = 0.f, zj0 = 0.f;
        float xj1 = 0.f, yj1 = 0.f, zj1 = 0.f;
        if (j < NATOMS) {
            const float4 c0 = *(const float4*)&sc[j * 8 + 0];
            const float4 c1 = *(const float4*)&sc[j * 8 + 4];
            xj0 = c0.x; yj0 = c0.y; zj0 = c0.z;
            xj1 = c1.x; yj1 = c1.y; zj1 = c1.z;
        }

        int i   = jbase + 1 + wid;
        int off = i * (i - 1) / 2 + jbase + lane;

        #pragma unroll 4
        for (; i < NATOMS; i += NWARPS, off += 8 * i - 36) {
            const bool valid = lane < (i - jbase);

            // v from SMEM: 29-cyc latency, no DRAM stall
            float v0 = 0.0f, v1 = 0.0f;
            if (valid) {
                v0 = sflat[off];
                v1 = sflat[off + NC2];
            }

            const float4 ci0 = *(const float4*)&sc[i * 8 + 0];
            const float4 ci1 = *(const float4*)&sc[i * 8 + 4];

            float dx0 = ci0.x - xj0, dy0 = ci0.y - yj0, dz0 = ci0.z - zj0;
            float dx1 = ci1.x - xj1, dy1 = ci1.y - yj1, dz1 = ci1.z - zj1;
            float r20 = fmaf(dx0, dx0, fmaf(dy0, dy0, dz0 * dz0));
            float r21 = fmaf(dx1, dx1, fmaf(dy1, dy1, dz1 * dz1));

            if (valid) {
                acc0 = fmaf(v0, rsqrtf(r20), acc0);
                acc1 = fmaf(v1, rsqrtf(r21), acc1);
            }
        }
    }

    // reductions
    #pragma unroll
    for (int off = 16; off > 0; off >>= 1) {
        acc0 += __shfl_down_sync(0xFFFFFFFFu, acc0, off);
        acc1 += __shfl_down_sync(0xFFFFFFFFu, acc1, off);
    }
    if (lane == 0) { wred[0][wid] = acc0; wred[1][wid] = acc1; }
    __syncthreads();

    if (wid == 0 && lane < NWARPS) {
        float s0 = wred[0][lane];
        float s1 = wred[1][lane];
        #pragma unroll
        for (int off = NWARPS / 2; off > 0; off >>= 1) {
            s0 += __shfl_down_sync(0xFFu, s0, off);
            s1 += __shfl_down_sync(0xFFu, s1, off);
        }
        if (lane == 0) { out[b0] = s0; out[b0 + 1] = s1; }
    }
}

extern "C" void kernel_launch(void* const* d_in, const int* in_sizes, int n_in,
                              void* d_out, int out_size)
{
    const float* coords = (const float*)d_in[0];   // [2048, 100, 3]
    const float* flat   = (const float*)d_in[1];   // [2048, 4950]
    float* out          = (float*)d_out;           // [2048, 1]

    eij_kernel<<<BATCH / BPB, TPB>>>(coords, flat, out);
}